// round 1
// baseline (speedup 1.0000x reference)
#include <cuda_runtime.h>

// Problem constants (from reference): x [B=4096, T=512, D=4], H=32, 2 LSTM layers,
// gate row order i,f,g,o (rows 0..127 of the 4H weight matrices), final [B,1] head.
#define TT 512
#define DD 4

__device__ __forceinline__ float fsig(float x) {
    // sigmoid via MUFU EX2 + MUFU RCP (abs err ~1e-6)
    return __fdividef(1.0f, 1.0f + __expf(-x));
}
__device__ __forceinline__ float ftanh(float x) {
    // tanh(x) = 1 - 2/(exp(2x)+1); exact limits at +/-inf of exp
    return 1.0f - __fdividef(2.0f, __expf(2.0f * x) + 1.0f);
}

__global__ __launch_bounds__(128, 4)
void lstm2_kernel(const float* __restrict__ x,
                  const float* __restrict__ Wih0, const float* __restrict__ Whh0,
                  const float* __restrict__ bih0, const float* __restrict__ bhh0,
                  const float* __restrict__ Wih1, const float* __restrict__ Whh1,
                  const float* __restrict__ bih1, const float* __restrict__ bhh1,
                  const float* __restrict__ Wout, const float* __restrict__ bout,
                  float* __restrict__ out)
{
    const int b    = blockIdx.x;
    const int tid  = threadIdx.x;   // == gate-row index (0..127): rows i,f,g,o
    const int gate = tid >> 5;      // warp 0:i 1:f 2:g 3:o  (activation warp-uniform)
    const int lane = tid & 31;      // hidden unit

    __shared__ __align__(16) float h0s[32];
    __shared__ __align__(16) float h1s[32];
    __shared__ float ga0[128];
    __shared__ float ga1[128];

    // ---- weights into registers (stay resident for the whole recurrence) ----
    float wih0[4], whh0[32], wih1[32], whh1[32];
    {
        float4 w = *reinterpret_cast<const float4*>(Wih0 + tid * 4);
        wih0[0] = w.x; wih0[1] = w.y; wih0[2] = w.z; wih0[3] = w.w;
        const float4* r0 = reinterpret_cast<const float4*>(Whh0 + tid * 32);
        const float4* r1 = reinterpret_cast<const float4*>(Wih1 + tid * 32);
        const float4* r2 = reinterpret_cast<const float4*>(Whh1 + tid * 32);
        #pragma unroll
        for (int k = 0; k < 8; ++k) {
            float4 a = r0[k];
            whh0[4*k+0] = a.x; whh0[4*k+1] = a.y; whh0[4*k+2] = a.z; whh0[4*k+3] = a.w;
            float4 c = r1[k];
            wih1[4*k+0] = c.x; wih1[4*k+1] = c.y; wih1[4*k+2] = c.z; wih1[4*k+3] = c.w;
            float4 d = r2[k];
            whh1[4*k+0] = d.x; whh1[4*k+1] = d.y; whh1[4*k+2] = d.z; whh1[4*k+3] = d.w;
        }
    }
    const float bias0 = bih0[tid] + bhh0[tid];
    const float bias1 = bih1[tid] + bhh1[tid];

    if (tid < 32) { h0s[tid] = 0.0f; h1s[tid] = 0.0f; }
    __syncthreads();

    float c0 = 0.0f, c1 = 0.0f;
    const float* xb = x + (size_t)b * (TT * DD);
    float4 xv = *reinterpret_cast<const float4*>(xb);   // x[b, 0, :]

    const float4* H0 = reinterpret_cast<const float4*>(h0s);
    const float4* H1 = reinterpret_cast<const float4*>(h1s);

    for (int t = 0; t < TT; ++t) {
        // ---------- layer 0 pre-activation: bias + x·Wih0 + h0·Whh0 ----------
        float s0 = fmaf(xv.x, wih0[0], bias0);
        float s1 = xv.y * wih0[1];
        float s2 = xv.z * wih0[2];
        float s3 = xv.w * wih0[3];
        #pragma unroll
        for (int k = 0; k < 8; ++k) {
            float4 h = H0[k];                       // broadcast LDS.128
            s0 = fmaf(h.x, whh0[4*k+0], s0);
            s1 = fmaf(h.y, whh0[4*k+1], s1);
            s2 = fmaf(h.z, whh0[4*k+2], s2);
            s3 = fmaf(h.w, whh0[4*k+3], s3);
        }
        float pre0 = (s0 + s1) + (s2 + s3);

        // prefetch next timestep's input while the gate exchange happens
        if (t + 1 < TT) xv = *reinterpret_cast<const float4*>(xb + (t + 1) * DD);

        ga0[tid] = (gate == 2) ? ftanh(pre0) : fsig(pre0);
        __syncthreads();                            // barrier 1: gate exchange L0

        // redundant per-warp update of (c0, h0) for unit `lane` — no 2nd barrier
        {
            float gi = ga0[lane], gf = ga0[32 + lane], gg = ga0[64 + lane], go = ga0[96 + lane];
            c0 = fmaf(gf, c0, gi * gg);
            h0s[lane] = go * ftanh(c0);             // identical value from all 4 warps
        }
        __syncwarp();                               // own warp wrote all 32 entries

        // ---------- layer 1 pre-activation: bias + h0·Wih1 + h1·Whh1 ----------
        float u0 = bias1, u1 = 0.0f, u2 = 0.0f, u3 = 0.0f;
        #pragma unroll
        for (int k = 0; k < 8; ++k) {
            float4 a = H0[k];
            float4 h = H1[k];
            u0 = fmaf(a.x, wih1[4*k+0], u0);
            u1 = fmaf(a.y, wih1[4*k+1], u1);
            u2 = fmaf(a.z, wih1[4*k+2], u2);
            u3 = fmaf(a.w, wih1[4*k+3], u3);
            u0 = fmaf(h.x, whh1[4*k+0], u0);
            u1 = fmaf(h.y, whh1[4*k+1], u1);
            u2 = fmaf(h.z, whh1[4*k+2], u2);
            u3 = fmaf(h.w, whh1[4*k+3], u3);
        }
        float pre1 = (u0 + u1) + (u2 + u3);

        ga1[tid] = (gate == 2) ? ftanh(pre1) : fsig(pre1);
        __syncthreads();                            // barrier 2: gate exchange L1

        {
            float gi = ga1[lane], gf = ga1[32 + lane], gg = ga1[64 + lane], go = ga1[96 + lane];
            c1 = fmaf(gf, c1, gi * gg);
            h1s[lane] = go * ftanh(c1);
        }
        __syncwarp();
    }

    // ---------- output head: out[b] = h1(final) · Wout + bout ----------
    if (tid < 32) {
        float v = h1s[lane] * Wout[lane];
        #pragma unroll
        for (int o = 16; o > 0; o >>= 1)
            v += __shfl_down_sync(0xffffffffu, v, o);
        if (lane == 0) out[b] = v + bout[0];
    }
}

extern "C" void kernel_launch(void* const* d_in, const int* in_sizes, int n_in,
                              void* d_out, int out_size)
{
    const float* x    = (const float*)d_in[0];
    const float* Wih0 = (const float*)d_in[1];
    const float* Whh0 = (const float*)d_in[2];
    const float* bih0 = (const float*)d_in[3];
    const float* bhh0 = (const float*)d_in[4];
    const float* Wih1 = (const float*)d_in[5];
    const float* Whh1 = (const float*)d_in[6];
    const float* bih1 = (const float*)d_in[7];
    const float* bhh1 = (const float*)d_in[8];
    const float* Wout = (const float*)d_in[9];
    const float* bout = (const float*)d_in[10];

    const int B = out_size;  // [B, 1] output, B = 4096
    lstm2_kernel<<<B, 128>>>(x, Wih0, Whh0, bih0, bhh0,
                             Wih1, Whh1, bih1, bhh1,
                             Wout, bout, (float*)d_out);
}